// round 16
// baseline (speedup 1.0000x reference)
#include <cuda_runtime.h>
#include <cuda_bf16.h>
#include <cstdint>

// IoU kernel: elementwise over N boxes, A=5 anchors.
// Inputs (metadata order):
//   d_in[0]: cell_nos  int32  [N,2]
//   d_in[1]: output    float  [N,5,5]
//   d_in[2]: target    float  [N,5]
// Output: float [N,5]
//
// One-shot CTA swarm (best measured architecture), refined:
//  - TMA bulk loads + bulk store carry L2::evict_first cache hints
//    (zero-reuse 592MB stream: insert evict-first, flush dirty lines early)
//  - stage holds output+target (30720B); cell_nos via per-thread __ldcs int2
//  - early issue: t0 runs mbar init -> fence -> expect_tx -> bulk copies all
//    before __syncthreads
//  - results overwrite s_tgt in place; one bulk smem->gmem store per CTA.

#define YI 20.0f
#define BPB 256           // boxes per tile == threads per block
#define A 5               // anchors

#define OUT_BYTES (BPB * 25 * 4)   // 25600
#define TGT_BYTES (BPB * 5 * 4)    //  5120 (doubles as result buffer)
#define STAGE_BYTES (OUT_BYTES + TGT_BYTES)   // 30720

__global__ __launch_bounds__(BPB) void iou_kernel(
    const int2* __restrict__ cell_nos,
    const float* __restrict__ output,
    const float* __restrict__ target,
    float* __restrict__ res,
    int n)
{
    __shared__ alignas(16) float s_out[BPB * 25];   // 25600 B
    __shared__ alignas(16) float s_tgt[BPB * 5];    //  5120 B (result buffer too)
    __shared__ alignas(8)  unsigned long long mbar;

    const int tid  = threadIdx.x;
    const int base = blockIdx.x * BPB;
    const bool full = (base + BPB <= n);
    const int box  = base + tid;

    const uint32_t mbar_a = (uint32_t)__cvta_generic_to_shared(&mbar);
    const uint32_t so_a   = (uint32_t)__cvta_generic_to_shared(s_out);
    const uint32_t st_a   = (uint32_t)__cvta_generic_to_shared(s_tgt);

    if (full) {
        // Per-thread cell load, issued immediately: latency hides under the
        // TMA wait below. Coalesced 8B/thread streaming load.
        const int2 cell = __ldcs(&cell_nos[box]);

        // t0: init mbar, fence, and issue both bulk loads BEFORE the barrier,
        // with an evict-first L2 policy (pure streaming, zero reuse).
        if (tid == 0) {
            asm volatile("mbarrier.init.shared::cta.b64 [%0], 1;"
                         :: "r"(mbar_a) : "memory");
            asm volatile("fence.proxy.async.shared::cta;" ::: "memory");
            asm volatile("mbarrier.arrive.expect_tx.shared::cta.b64 _, [%0], %1;"
                         :: "r"(mbar_a), "r"((uint32_t)STAGE_BYTES) : "memory");
            uint64_t pol;
            asm volatile("createpolicy.fractional.L2::evict_first.b64 %0, 1.0;"
                         : "=l"(pol));
            asm volatile("cp.async.bulk.shared::cta.global.mbarrier::complete_tx::bytes"
                         ".L2::cache_hint [%0], [%1], %2, [%3], %4;"
                         :: "r"(so_a), "l"(output + (size_t)base * 25),
                            "r"((uint32_t)OUT_BYTES), "r"(mbar_a), "l"(pol) : "memory");
            asm volatile("cp.async.bulk.shared::cta.global.mbarrier::complete_tx::bytes"
                         ".L2::cache_hint [%0], [%1], %2, [%3], %4;"
                         :: "r"(st_a), "l"(target + (size_t)base * 5),
                            "r"((uint32_t)TGT_BYTES), "r"(mbar_a), "l"(pol) : "memory");
        }
        __syncthreads();   // mbar init visible to all threads before polling

        // Wait for TMA delivery (phase 0), acquire ordering for ld.shared.
        {
            uint32_t done;
            asm volatile(
                "{\n\t"
                ".reg .pred p;\n\t"
                "mbarrier.try_wait.parity.acquire.cta.shared::cta.b64 p, [%1], 0;\n\t"
                "selp.b32 %0, 1, 0, p;\n\t"
                "}"
                : "=r"(done) : "r"(mbar_a) : "memory");
            if (!done) {
                asm volatile(
                    "{\n\t"
                    ".reg .pred P1;\n\t"
                    "WAIT_LOOP_%=:\n\t"
                    "mbarrier.try_wait.parity.acquire.cta.shared::cta.b64 P1, [%0], 0, 0x989680;\n\t"
                    "@P1 bra.uni WAIT_DONE_%=;\n\t"
                    "bra.uni WAIT_LOOP_%=;\n\t"
                    "WAIT_DONE_%=:\n\t"
                    "}"
                    :: "r"(mbar_a) : "memory");
            }
        }

        // ---- compute; results overwrite s_tgt in place ----
        {
            const float ci = (float)cell.x * YI + YI * 0.5f;
            const float cj = (float)cell.y * YI + YI * 0.5f;

            const float* t = &s_tgt[5 * tid];
            const float g_h = t[3] * YI, g_w = t[4] * YI;
            const float gxc = ci + t[1] * YI;
            const float gyc = cj + t[2] * YI;
            const float gx1 = gyc - g_w * 0.5f;
            const float gy1 = gxc - g_h * 0.5f;
            const float gx2 = gyc + g_w * 0.5f;
            const float gy2 = gxc + g_h * 0.5f;
            const float area_g = (gx2 - gx1) * (gy2 - gy1);

            float r[A];
            #pragma unroll
            for (int a = 0; a < A; a++) {
                const float* o = &s_out[25 * tid + 5 * a];
                const float p_h = o[3] * YI, p_w = o[4] * YI;
                const float pxc = ci + o[1] * YI;
                const float pyc = cj + o[2] * YI;
                const float px1 = pyc - p_w * 0.5f;
                const float py1 = pxc - p_h * 0.5f;
                const float px2 = pyc + p_w * 0.5f;
                const float py2 = pxc + p_h * 0.5f;
                const float area_p = (px2 - px1) * (py2 - py1);

                const float lx = fmaxf(px1, gx1);
                const float ly = fmaxf(py1, gy1);
                const float rx = fminf(px2, gx2);
                const float ry = fminf(py2, gy2);
                const float iw = fmaxf(rx - lx, 0.0f);
                const float ih = fmaxf(ry - ly, 0.0f);
                const float inter = iw * ih;
                const float uni = area_p + area_g - inter;
                r[a] = __fdividef(inter, uni);
            }
            // Thread tid overwrites exactly [5*tid, 5*tid+5), which only it
            // read above -> no cross-thread hazard.
            #pragma unroll
            for (int a = 0; a < A; a++) s_tgt[5 * tid + a] = r[a];
        }
        __syncthreads();   // all results staged

        if (tid == 0) {
            uint64_t pol;
            asm volatile("createpolicy.fractional.L2::evict_first.b64 %0, 1.0;"
                         : "=l"(pol));
            asm volatile("fence.proxy.async.shared::cta;" ::: "memory");
            asm volatile("cp.async.bulk.global.shared::cta.bulk_group"
                         ".L2::cache_hint [%0], [%1], %2, %3;"
                         :: "l"(res + (size_t)base * 5), "r"(st_a),
                            "r"((uint32_t)TGT_BYTES), "l"(pol) : "memory");
            asm volatile("cp.async.bulk.commit_group;" ::: "memory");
            asm volatile("cp.async.bulk.wait_group 0;" ::: "memory");
        }
    } else if (box < n) {
        // Tail block (never taken at bench shape N=4,000,000=15625*256):
        // direct scalar path.
        const int2 cell = cell_nos[box];
        const float ci = (float)cell.x * YI + YI * 0.5f;
        const float cj = (float)cell.y * YI + YI * 0.5f;
        const float* t = target + (size_t)box * 5;
        const float g_h = t[3] * YI, g_w = t[4] * YI;
        const float gxc = ci + t[1] * YI;
        const float gyc = cj + t[2] * YI;
        const float gx1 = gyc - g_w * 0.5f;
        const float gy1 = gxc - g_h * 0.5f;
        const float gx2 = gyc + g_w * 0.5f;
        const float gy2 = gxc + g_h * 0.5f;
        const float area_g = (gx2 - gx1) * (gy2 - gy1);
        #pragma unroll
        for (int a = 0; a < A; a++) {
            const float* o = output + (size_t)box * 25 + 5 * a;
            const float p_h = o[3] * YI, p_w = o[4] * YI;
            const float pxc = ci + o[1] * YI;
            const float pyc = cj + o[2] * YI;
            const float px1 = pyc - p_w * 0.5f;
            const float py1 = pxc - p_h * 0.5f;
            const float px2 = pyc + p_w * 0.5f;
            const float py2 = pxc + p_h * 0.5f;
            const float area_p = (px2 - px1) * (py2 - py1);
            const float lx = fmaxf(px1, gx1);
            const float ly = fmaxf(py1, gy1);
            const float rx = fminf(px2, gx2);
            const float ry = fminf(py2, gy2);
            const float iw = fmaxf(rx - lx, 0.0f);
            const float ih = fmaxf(ry - ly, 0.0f);
            const float inter = iw * ih;
            res[(size_t)box * 5 + a] = __fdividef(inter, area_p + area_g - inter);
        }
    }
}

extern "C" void kernel_launch(void* const* d_in, const int* in_sizes, int n_in,
                              void* d_out, int out_size) {
    const int2*  cell_nos = (const int2*)d_in[0];
    const float* output   = (const float*)d_in[1];
    const float* target   = (const float*)d_in[2];
    float*       res      = (float*)d_out;

    const int n = in_sizes[0] / 2;  // cell_nos is [N,2]
    const int grid = (n + BPB - 1) / BPB;
    iou_kernel<<<grid, BPB>>>(cell_nos, output, target, res, n);
}